// round 12
// baseline (speedup 1.0000x reference)
#include <cuda_runtime.h>
#include <cstdint>

// ---------------------------------------------------------------------------
// DiverseRegDCConv2d: per-sample dynamically-generated 3x3 conv.
//   wgen[b,o,c,kh,kw] = sum_n se[b,n] * weight[(o*C+c)*9+kh*3+kw, n]
//   out[b,o,h,w] = sum_{c,kh,kw} wgen[b,o,c,kh,kw] * x[b,c,h+kh-1,w+kw-1] + bias[o]
// B=32, C=O=256, H=W=28, K=3, NUM=8.
// ---------------------------------------------------------------------------

#define BB   32
#define CIN  256
#define COUT 256
#define HH   28
#define WW   28

typedef unsigned long long ULL;

// Stage-1 output: generated weights, o-major per tap for conflict-free LDS:
//   [b][ob:8][c:256][tap:9][o31:32]  (75.5 MB)
__device__ float g_wT[(size_t)BB * 8 * 256 * 9 * 32];
// Stage-0 output: input rows in dual alignment, cp16-ready (58.7 MB):
//   [b][c][h][64]: f0..27 = cols 0..27 | f28..31 = 0 | f32 = 0 (col -1) |
//                  f33..60 = cols 0..27 | f61..63 = 0
__device__ float g_xpad[(size_t)BB * CIN * HH * 64];

__device__ __forceinline__ ULL pack2(float lo, float hi) {
    ULL r; asm("mov.b64 %0, {%1, %2};" : "=l"(r) : "f"(lo), "f"(hi)); return r;
}
__device__ __forceinline__ ULL ffma2(ULL a, ULL b, ULL c) {
    ULL d; asm("fma.rn.f32x2 %0, %1, %2, %3;" : "=l"(d) : "l"(a), "l"(b), "l"(c)); return d;
}
__device__ __forceinline__ ULL fadd2(ULL a, ULL b) {
    ULL d; asm("add.rn.f32x2 %0, %1, %2;" : "=l"(d) : "l"(a), "l"(b)); return d;
}
__device__ __forceinline__ float2 unpack2(ULL v) {
    float2 f; asm("mov.b64 {%0, %1}, %2;" : "=f"(f.x), "=f"(f.y) : "l"(v)); return f;
}
__device__ __forceinline__ void cp16(uint32_t dst, const void* src) {
    asm volatile("cp.async.ca.shared.global [%0], [%1], 16;\n"
                 :: "r"(dst), "l"(src) : "memory");
}
#define CP_COMMIT() asm volatile("cp.async.commit_group;\n" ::: "memory")
#define CP_WAIT0()  asm volatile("cp.async.wait_group 0;\n" ::: "memory")

// ---------------------------------------------------------------------------
// Stage 0: build dual-aligned padded input rows (pure-cp16 conv fills).
// ---------------------------------------------------------------------------
__global__ void xpad_kernel(const float* __restrict__ x) {
    int gid = blockIdx.x * 256 + threadIdx.x;     // < 3,670,016
    int row = gid >> 4;                            // (b*256+c)*28+h
    int s   = gid & 15;
    const float* src = x + (size_t)row * WW;
    float4 v;
    if (s < 7) {
        v = *(const float4*)(src + 4 * s);         // cols 4s..4s+3 (aligned)
    } else if (s == 7) {
        v = make_float4(0.f, 0.f, 0.f, 0.f);
    } else {
        float t[4];
        #pragma unroll
        for (int m = 0; m < 4; ++m) {
            int col = 4 * s + m - 33;              // f = 4s+m, col = f-33
            t[m] = ((unsigned)col < (unsigned)WW) ? __ldg(src + col) : 0.f;
        }
        v = make_float4(t[0], t[1], t[2], t[3]);
    }
    *(float4*)(g_xpad + (size_t)row * 64 + 4 * s) = v;
}

// ---------------------------------------------------------------------------
// Stage 1: weight generation, written o-major per tap.
// Block = one (ob, c): 288 threads = 32 o31 x 9 taps; loops over 32 samples.
// ---------------------------------------------------------------------------
__global__ void wgen_kernel(const float* __restrict__ wbank,
                            const float* __restrict__ se) {
    __shared__ float s_se[BB * 8];
    __shared__ float sm[288];
    int tid = threadIdx.x;                 // 0..287
    if (tid < 256) s_se[tid] = se[tid];
    __syncthreads();

    const int c   = blockIdx.x & 255;
    const int ob  = blockIdx.x >> 8;       // 0..7
    const int o31 = tid / 9;
    const int t   = tid % 9;
    const int o   = ob * 32 + o31;

    const float4* src = (const float4*)wbank + ((size_t)(o * CIN + c) * 9 + t) * 2;
    float4 w0 = src[0];
    float4 w1 = src[1];

    float* dst0 = g_wT + (size_t)c * 288 + tid;
    for (int b = 0; b < BB; ++b) {
        const float* s = &s_se[b * 8];
        float v = w0.x * s[0];
        v = fmaf(w0.y, s[1], v);
        v = fmaf(w0.z, s[2], v);
        v = fmaf(w0.w, s[3], v);
        v = fmaf(w1.x, s[4], v);
        v = fmaf(w1.y, s[5], v);
        v = fmaf(w1.z, s[6], v);
        v = fmaf(w1.w, s[7], v);
        sm[t * 32 + o31] = v;
        __syncthreads();
        dst0[(size_t)(b * 8 + ob) * 256 * 288] = sm[tid];   // coalesced 288 floats
        __syncthreads();
    }
}

// ---------------------------------------------------------------------------
// Stage 2: direct conv. Block (16,14)=224 thr = 32 o x 14 rows x 28 cols.
// Thread: 4 o-channels (olane+8*oo) x 1 row (ty) x half-row (xh = tx>>3).
// acc = 4 x 7 f32x2. Per (cc,r): 15 input LDS.64 + 12 weight LDS.32 +
// 12 packs + 84 FFMA2 -> LSU/FMA = 0.32 (was 0.64).
// SMEM input row (XR=72 floats, 72 % 32 = 8 -> conflict-free across rows):
//   A at f0..27 (col c @ f c), B at f36..67 (col c @ f 37+c; f36 = col -1 = 0)
// Weights in smem o-major: [cc][tap:9][o:32] -> broadcast LDS.32, 1 wavefront.
// ---------------------------------------------------------------------------
#define CCK  4                       // channels per chunk (64 chunks)
#define NRW  16                      // staged rows (14 + 2 halo)
#define XR   72                      // floats per staged input row
#define XCH  (CCK * NRW * XR)        // 4608 floats per input buffer
#define WCH  (CCK * 9 * 32)          // 1152 floats per weight buffer
#define SMEM_BYTES ((2 * WCH + 2 * XCH) * 4)   // 9216 + 36864 = 46080 B

__global__ __launch_bounds__(224, 3)
void dconv_kernel(const float* __restrict__ bias,
                  float* __restrict__ out) {
    extern __shared__ float smem[];
    float* ws = smem;                // [2][WCH]
    float* xs = smem + 2 * WCH;      // [2][XCH]

    const int tx  = threadIdx.x;     // 0..15
    const int ty  = threadIdx.y;     // 0..13 : output row
    const int tid = ty * 16 + tx;
    const int olane = tx & 7;        // 0..7
    const int xh  = tx >> 3;         // col half
    const int j0  = 7 * xh;

    const int b       = blockIdx.y;
    const int ob      = blockIdx.x >> 1;   // 0..7
    const int rb      = blockIdx.x & 1;    // 0..1
    const int oBase   = ob * 32;
    const int rowBase = rb * 14;

    const float* wsrc = g_wT + (size_t)(b * 8 + ob) * 256 * 288;  // + c*288
    const float* xsrc = g_xpad + (size_t)b * CIN * HH * 64;

    const uint32_t ws_u = (uint32_t)__cvta_generic_to_shared(ws);
    const uint32_t xs_u = (uint32_t)__cvta_generic_to_shared(xs);

    // Zero input buffers once (invalid halo rows stay zero forever).
    for (int i = tid; i < (2 * XCH) / 4; i += 224)
        ((float4*)xs)[i] = make_float4(0.f, 0.f, 0.f, 0.f);
    __syncthreads();

    ULL acc0[7], acc1[7], acc2[7], acc3[7];
    #pragma unroll
    for (int j = 0; j < 7; ++j)
        { acc0[j] = 0ull; acc1[j] = 0ull; acc2[j] = 0ull; acc3[j] = 0ull; }

    // ---- prologue: fill chunk 0 into buffer 0 (all cp16)
    {
        for (int i = tid; i < 288; i += 224)               // weights: 4608B
            cp16(ws_u + i * 16, wsrc + i * 4);
        for (int i = tid; i < 960; i += 224) {             // input: 15 cp16/row
            int cc = i / 240, rem = i % 240, rw = rem / 15, s = rem % 15;
            int ih = rowBase - 1 + rw;
            if ((unsigned)ih < (unsigned)HH) {
                int dco = (s < 7) ? s * 4 : 36 + (s - 7) * 4;
                int sco = (s < 7) ? s * 4 : 32 + (s - 7) * 4;
                cp16(xs_u + ((cc * NRW + rw) * XR + dco) * 4,
                     xsrc + ((size_t)cc * HH + ih) * 64 + sco);
            }
        }
        CP_COMMIT();
    }

    for (int k = 0; k < CIN / CCK; ++k) {
        CP_WAIT0();
        __syncthreads();

        if (k < CIN / CCK - 1) {
            const int c0 = (k + 1) * CCK;
            const uint32_t wd = ws_u + ((k + 1) & 1) * (WCH * 4);
            const uint32_t xd = xs_u + ((k + 1) & 1) * (XCH * 4);
            const float* wsk = wsrc + (size_t)c0 * 288;
            for (int i = tid; i < 288; i += 224)
                cp16(wd + i * 16, wsk + i * 4);
            for (int i = tid; i < 960; i += 224) {
                int cc = i / 240, rem = i % 240, rw = rem / 15, s = rem % 15;
                int ih = rowBase - 1 + rw;
                if ((unsigned)ih < (unsigned)HH) {
                    int dco = (s < 7) ? s * 4 : 36 + (s - 7) * 4;
                    int sco = (s < 7) ? s * 4 : 32 + (s - 7) * 4;
                    cp16(xd + ((cc * NRW + rw) * XR + dco) * 4,
                         xsrc + ((size_t)(c0 + cc) * HH + ih) * 64 + sco);
                }
            }
            CP_COMMIT();
        }

        const float* wsb = ws + (k & 1) * WCH;
        const float* xsb = xs + (k & 1) * XCH;

        #pragma unroll
        for (int cc = 0; cc < CCK; ++cc) {
            #pragma unroll
            for (int r = 0; r < 3; ++r) {
                const float* wp = wsb + (cc * 9 + r * 3) * 32 + olane;
                // 12 broadcast LDS.32 + 12 packs (ALU pipe, has headroom)
                ULL W00 = pack2(wp[0],      wp[0]);
                ULL W01 = pack2(wp[8],      wp[8]);
                ULL W02 = pack2(wp[16],     wp[16]);
                ULL W03 = pack2(wp[24],     wp[24]);
                ULL W10 = pack2(wp[32],     wp[32]);
                ULL W11 = pack2(wp[40],     wp[40]);
                ULL W12 = pack2(wp[48],     wp[48]);
                ULL W13 = pack2(wp[56],     wp[56]);
                ULL W20 = pack2(wp[64],     wp[64]);
                ULL W21 = pack2(wp[72],     wp[72]);
                ULL W22 = pack2(wp[80],     wp[80]);
                ULL W23 = pack2(wp[88],     wp[88]);
                const float* xr = xsb + (cc * NRW + ty + r) * XR;
                const ULL* Aq = (const ULL*)xr;
                const ULL* Bq = (const ULL*)(xr + 36);
                ULL b0 = Bq[j0];
                #pragma unroll
                for (int jj = 0; jj < 7; ++jj) {
                    ULL a  = Aq[j0 + jj];
                    ULL b1 = Bq[j0 + jj + 1];
                    acc0[jj] = ffma2(W20, b1, ffma2(W10, a, ffma2(W00, b0, acc0[jj])));
                    acc1[jj] = ffma2(W21, b1, ffma2(W11, a, ffma2(W01, b0, acc1[jj])));
                    acc2[jj] = ffma2(W22, b1, ffma2(W12, a, ffma2(W02, b0, acc2[jj])));
                    acc3[jj] = ffma2(W23, b1, ffma2(W13, a, ffma2(W03, b0, acc3[jj])));
                    b0 = b1;
                }
            }
        }
    }

    // ---- epilogue: bias + store (4 o x 7 float2 each)
    const int h = rowBase + ty;
    #pragma unroll
    for (int oo = 0; oo < 4; ++oo) {
        ULL* ap = (oo == 0) ? acc0 : (oo == 1) ? acc1 : (oo == 2) ? acc2 : acc3;
        int o = oBase + olane + 8 * oo;
        float bv = bias[o];
        ULL bb = pack2(bv, bv);
        float2* p = (float2*)(out + (((size_t)b * COUT + o) * HH + h) * WW + 2 * j0);
        #pragma unroll
        for (int jj = 0; jj < 7; ++jj)
            p[jj] = unpack2(fadd2(ap[jj], bb));
    }
}

// ---------------------------------------------------------------------------
// Harness entry. Inputs (metadata order): inputs, inputs_se, weight, bias.
// ---------------------------------------------------------------------------
extern "C" void kernel_launch(void* const* d_in, const int* in_sizes, int n_in,
                              void* d_out, int out_size) {
    const float* x    = (const float*)d_in[0];   // [32,256,28,28]
    const float* se   = (const float*)d_in[1];   // [32,8]
    const float* wbk  = (const float*)d_in[2];   // [589824,8]
    const float* bias = (const float*)d_in[3];   // [256]
    float* out = (float*)d_out;                  // [32,256,28,28]

    cudaFuncSetAttribute(dconv_kernel,
                         cudaFuncAttributePreferredSharedMemoryCarveout, 100);

    xpad_kernel<<<(BB * CIN * HH * 16) / 256, 256>>>(x);   // 14336 blocks
    wgen_kernel<<<8 * 256, 288>>>(wbk, se);                // 2048 blocks

    dim3 grid(16, BB);          // x: 8 o-blocks * 2 row-halves, y: batch
    dim3 block(16, 14);         // 224 threads
    dconv_kernel<<<grid, block, SMEM_BYTES>>>(bias, out);
}